// round 13
// baseline (speedup 1.0000x reference)
#include <cuda_runtime.h>
#include <math.h>

#define Bsz  32
#define Tlen 512
#define Idim 1024
#define Hdim 1024
#define G4   4096
#define NBLK 128

// ---------------- device scratch ----------------
__device__ float g_xw[(size_t)Tlen * Bsz * G4];       // [t][b][4H]
// A fragment-major: [MT 1024][KT 128][lane 32] x float4  (k8 granule)
__device__ float4 g_xa[(size_t)1024 * 128 * 32];
// B (W_ih) fragment-major: [NT 512][KT2 64][lane 32] x float4 (k16 granule)
__device__ float4 g_wb[(size_t)512 * 64 * 32];
__device__ float g_hA[2][2][128][32][4];              // h A-frag layout (tf32 bits)
__device__ unsigned int g_bar;

// ---------------- helpers ----------------
__device__ __forceinline__ unsigned f2tf32(float f)
{
    unsigned r;
    asm("cvt.rna.tf32.f32 %0, %1;" : "=r"(r) : "f"(f));
    return r;
}
__device__ __forceinline__ void mma_tf32(float* d, const unsigned* a, const unsigned* b)
{
    asm volatile(
        "mma.sync.aligned.m16n8k8.row.col.f32.tf32.tf32.f32 "
        "{%0,%1,%2,%3},{%4,%5,%6,%7},{%8,%9},{%0,%1,%2,%3};"
        : "+f"(d[0]), "+f"(d[1]), "+f"(d[2]), "+f"(d[3])
        : "r"(a[0]), "r"(a[1]), "r"(a[2]), "r"(a[3]), "r"(b[0]), "r"(b[1]));
}
__device__ __forceinline__ void cp_async16(unsigned dst, const void* src)
{
    asm volatile("cp.async.cg.shared.global [%0], [%1], 16;" :: "r"(dst), "l"(src));
}
#define CP_COMMIT()  asm volatile("cp.async.commit_group;")
#define CP_WAIT(N)   asm volatile("cp.async.wait_group %0;" :: "n"(N))

__device__ __forceinline__ uint4 lds128(unsigned addr)
{
    uint4 v;
    asm volatile("ld.shared.v4.b32 {%0,%1,%2,%3}, [%4];"
                 : "=r"(v.x), "=r"(v.y), "=r"(v.z), "=r"(v.w) : "r"(addr));
    return v;
}
__device__ __forceinline__ float sig_fast(float x)
{
    return __frcp_rn(1.f + __expf(-x));
}
__device__ __forceinline__ float tanh_fast(float x)
{
    return fmaf(2.f, __frcp_rn(1.f + __expf(-2.f * x)), -1.f);
}

// =======================================================================
// Kernel 0: build fragment-major tf32-rounded copies of x and W_ih.
// =======================================================================
__global__ void __launch_bounds__(256) prep_kernel(
    const float* __restrict__ x, const float* __restrict__ Wih)
{
    if (blockIdx.x == 0 && threadIdx.x == 0) g_bar = 0u;
    const size_t NA = (size_t)1024 * 128 * 32;
    const size_t NW = (size_t)512 * 64 * 32;
    size_t i0 = (size_t)blockIdx.x * blockDim.x + threadIdx.x;
    size_t stride = (size_t)gridDim.x * blockDim.x;

    for (size_t i = i0; i < NA; i += stride) {
        int l  = (int)(i & 31);
        int KT = (int)((i >> 5) & 127);
        int MT = (int)(i >> 12);
        int g = l >> 2, tg = l & 3;
        const float* base = x + (size_t)(MT * 16 + g) * Idim + KT * 8 + tg;
        uint4 r;
        r.x = f2tf32(base[0]);
        r.y = f2tf32(base[8 * Idim]);
        r.z = f2tf32(base[4]);
        r.w = f2tf32(base[8 * Idim + 4]);
        *(uint4*)&g_xa[i] = r;
    }
    for (size_t i = i0; i < NW; i += stride) {
        int l   = (int)(i & 31);
        int KT2 = (int)((i >> 5) & 63);
        int NT  = (int)(i >> 11);
        int g = l >> 2, tg = l & 3;
        const float* base = Wih + (size_t)(NT * 8 + g) * Idim + KT2 * 16 + tg;
        uint4 r;
        r.x = f2tf32(base[0]);
        r.y = f2tf32(base[4]);
        r.z = f2tf32(base[8]);
        r.w = f2tf32(base[12]);
        *(uint4*)&g_wb[i] = r;
    }
}

// =======================================================================
// Phase 1: g_xw = x @ Wih^T + b. tf32 mma.sync.
// CTA tile 128(M) x 128(N), chunk K=16, 256 thr (8 warps = 4M x 2N),
// warp tile 32x64. A via 4-buffer cp.async ring (8KB/buf, smem);
// B fragments via __ldg from global (L1-dedup), prefetched 1 chunk ahead.
// Accumulation order identical to previous round (bitwise-same result).
// =======================================================================
#define P1_NBUF   4
#define P1_ABY    (8 * 2 * 32 * 16)       // 8192 bytes per stage
#define P1_SMEM   (P1_NBUF * P1_ABY)      // 32768

__device__ __forceinline__ void p1_stage(unsigned smb, int MT0, int kt2, int tid)
{
    const int buf = (kt2 & 3);
#pragma unroll
    for (int j = 0; j < 2; j++) {
        int item = tid + j * 256;                 // (mt*2+kt)*32 + l
        int mt = item >> 6, kt = (item >> 5) & 1, l = item & 31;
        const float4* src = g_xa + ((size_t)(MT0 + mt) * 128 + kt2 * 2 + kt) * 32 + l;
        cp_async16(smb + (unsigned)(buf * P1_ABY + item * 16), src);
    }
    CP_COMMIT();
}

__global__ void __launch_bounds__(256, 1) gemm_xw_kernel(const float* __restrict__ bias)
{
    extern __shared__ float sm[];

    const int tid  = threadIdx.x;
    const int wi   = tid >> 5;
    const int lane = tid & 31;
    const int wm   = wi >> 1;            // 0..3
    const int wn   = wi & 1;             // 0..1
    const int g    = lane >> 2;
    const int tg   = lane & 3;

    const int bn  = blockIdx.x * 128;
    const int bm  = blockIdx.y * 128;
    const int MT0 = blockIdx.y * 8;
    const int NT0 = blockIdx.x * 16;

    const unsigned smb = (unsigned)__cvta_generic_to_shared(sm);

    float D[2][8][4];
#pragma unroll
    for (int mi = 0; mi < 2; mi++)
#pragma unroll
        for (int ni = 0; ni < 8; ni++)
#pragma unroll
            for (int q = 0; q < 4; q++) D[mi][ni][q] = 0.f;

    // ---- prologue: A stages 0..2, B chunk 0 into registers ----
    p1_stage(smb, MT0, 0, tid);
    p1_stage(smb, MT0, 1, tid);
    p1_stage(smb, MT0, 2, tid);

    uint4 Bcur[8], Bnxt[8];
#pragma unroll
    for (int ni = 0; ni < 8; ni++)
        Bcur[ni] = __ldg((const uint4*)(g_wb +
            ((size_t)(NT0 + wn * 8 + ni) * 64 + 0) * 32 + lane));

    for (int kt2 = 0; kt2 < 64; kt2++) {
        // ensure A stage kt2 landed
        if (kt2 < 62)      { CP_WAIT(2); }
        else if (kt2 == 62){ CP_WAIT(1); }
        else               { CP_WAIT(0); }
        __syncthreads();

        // prefetch next B chunk
        if (kt2 + 1 < 64) {
#pragma unroll
            for (int ni = 0; ni < 8; ni++)
                Bnxt[ni] = __ldg((const uint4*)(g_wb +
                    ((size_t)(NT0 + wn * 8 + ni) * 64 + kt2 + 1) * 32 + lane));
        }
        // stage A chunk kt2+3 (slot (kt2+3)&3 = (kt2-1)&3: fully consumed)
        if (kt2 + 3 < 64) p1_stage(smb, MT0, kt2 + 3, tid);

        const unsigned Ab = smb + (unsigned)((kt2 & 3) * P1_ABY);
#pragma unroll
        for (int half = 0; half < 2; half++) {
            uint4 Aq[2];
#pragma unroll
            for (int mi = 0; mi < 2; mi++)
                Aq[mi] = lds128(Ab +
                    (unsigned)(((((wm * 2 + mi) * 2 + half)) * 32 + lane) * 16));
#pragma unroll
            for (int mi = 0; mi < 2; mi++)
#pragma unroll
                for (int ni = 0; ni < 8; ni++) {
                    unsigned bfrag[2];
                    bfrag[0] = half ? Bcur[ni].z : Bcur[ni].x;
                    bfrag[1] = half ? Bcur[ni].w : Bcur[ni].y;
                    mma_tf32(D[mi][ni], (const unsigned*)&Aq[mi], bfrag);
                }
        }
#pragma unroll
        for (int ni = 0; ni < 8; ni++) Bcur[ni] = Bnxt[ni];
    }

    // ---- epilogue: +bias, scatter to g_xw[t][b][n] ----
    float2 bv[8];
#pragma unroll
    for (int ni = 0; ni < 8; ni++) {
        int j0 = bn + wn * 64 + ni * 8 + tg * 2;
        bv[ni].x = __ldg(bias + j0);
        bv[ni].y = __ldg(bias + j0 + 1);
    }
#pragma unroll
    for (int mi = 0; mi < 2; mi++) {
        int r0 = bm + wm * 32 + mi * 16 + g;
        int r1 = r0 + 8;
        int t0 = r0 & (Tlen - 1), b0 = r0 >> 9;
        int t1 = r1 & (Tlen - 1), b1 = r1 >> 9;
        float* base0 = &g_xw[(size_t)t0 * (Bsz * G4) + (size_t)b0 * G4];
        float* base1 = &g_xw[(size_t)t1 * (Bsz * G4) + (size_t)b1 * G4];
#pragma unroll
        for (int ni = 0; ni < 8; ni++) {
            int j0 = bn + wn * 64 + ni * 8 + tg * 2;
            float2 v0; v0.x = D[mi][ni][0] + bv[ni].x; v0.y = D[mi][ni][1] + bv[ni].y;
            float2 v1; v1.x = D[mi][ni][2] + bv[ni].x; v1.y = D[mi][ni][3] + bv[ni].y;
            *(float2*)(base0 + j0) = v0;
            *(float2*)(base1 + j0) = v1;
        }
    }
}

// =======================================================================
// Phase 2: persistent tensor-core recurrence (UNCHANGED — at its floor).
// =======================================================================
#define SWB_FLOATS (4 * 128 * 32 * 2)           // 32768 (128 KB)
#define SPART_FLOATS (8 * 2 * 4 * 32 * 4)       // 4096  (16 KB)
#define SMEM_P2 ((SWB_FLOATS + SPART_FLOATS) * 4)

__device__ __forceinline__ void grid_barrier(unsigned target)
{
    __syncthreads();
    if (threadIdx.x == 0) {
        __threadfence();
        asm volatile("red.release.gpu.global.add.u32 [%0], %1;"
                     :: "l"(&g_bar), "r"(1u) : "memory");
        unsigned v;
        do {
            asm volatile("ld.acquire.gpu.global.u32 %0, [%1];"
                         : "=r"(v) : "l"(&g_bar) : "memory");
        } while (v < target);
    }
    __syncthreads();
}

__global__ void __launch_bounds__(256, 1) lstm_rec_kernel(
    const float* __restrict__ Whh, float* __restrict__ out)
{
    extern __shared__ float smemf[];
    float* sWB   = smemf;                // [g][kt][lane][2] tf32 B fragments
    float* sPart = smemf + SWB_FLOATS;   // [wi][mt][g][lane][4] fp32 partial D

    const int tid  = threadIdx.x;
    const int bid  = blockIdx.x;
    const int wi   = tid >> 5;
    const int lane = tid & 31;

    for (int idx = tid; idx < 4 * 128 * 32; idx += 256) {
        int l  = idx & 31;
        int kt = (idx >> 5) & 127;
        int g  = idx >> 12;
        int row = g * 1024 + bid * 8 + (l >> 2);
        int k0  = kt * 8 + (l & 3);
        unsigned* dst = (unsigned*)&sWB[((g * 128 + kt) * 32 + l) * 2];
        dst[0] = f2tf32(Whh[(size_t)row * Hdim + k0]);
        dst[1] = f2tf32(Whh[(size_t)row * Hdim + k0 + 4]);
    }

    const int rb = tid >> 3;
    const int rh = tid & 7;
    const int j  = bid * 8 + rh;

    const int p_mt   = rb >> 4;
    const int p_kt   = j >> 3;
    const int p_lane = (rb & 7) * 4 + (rh & 3);
    const int p_reg  = ((rb & 15) >> 3) + 2 * (rh >> 2);

    g_hA[0][p_mt][p_kt][p_lane][p_reg] = 0.f;

    const int laneD = (rb & 7) * 4 + (rh >> 1);
    const int regD  = (rh & 1) + 2 * ((rb & 15) >> 3);
    const int mtD   = rb >> 4;

    const float* xwp = g_xw + (size_t)rb * G4 + j;
    float xv[4];
#pragma unroll
    for (int g = 0; g < 4; g++) xv[g] = __ldg(xwp + g * 1024);

    float c_state = 0.f;
    unsigned target = NBLK;
    grid_barrier(target);

    const int kt0 = wi * 16;

    for (int t = 0; t < Tlen; t++) {
        const int rbuf = t & 1, wbuf = rbuf ^ 1;

        float D[2][4][4];
#pragma unroll
        for (int m = 0; m < 2; m++)
#pragma unroll
            for (int n = 0; n < 4; n++)
#pragma unroll
                for (int q = 0; q < 4; q++) D[m][n][q] = 0.f;

        uint4 A0 = __ldcg((const uint4*)&g_hA[rbuf][0][kt0][lane][0]);
        uint4 A1 = __ldcg((const uint4*)&g_hA[rbuf][1][kt0][lane][0]);
#pragma unroll
        for (int i = 0; i < 16; i++) {
            uint4 a0 = A0, a1 = A1;
            if (i < 15) {
                A0 = __ldcg((const uint4*)&g_hA[rbuf][0][kt0 + i + 1][lane][0]);
                A1 = __ldcg((const uint4*)&g_hA[rbuf][1][kt0 + i + 1][lane][0]);
            }
#pragma unroll
            for (int g = 0; g < 4; g++) {
                unsigned bfrag[2];
                *(uint2*)bfrag = *(const uint2*)&sWB[((g * 128 + kt0 + i) * 32 + lane) * 2];
                mma_tf32(D[0][g], (const unsigned*)&a0, bfrag);
                mma_tf32(D[1][g], (const unsigned*)&a1, bfrag);
            }
        }

#pragma unroll
        for (int m = 0; m < 2; m++)
#pragma unroll
            for (int g = 0; g < 4; g++)
                *(float4*)&sPart[(((wi * 2 + m) * 4 + g) * 32 + lane) * 4] =
                    *(float4*)D[m][g];
        __syncthreads();

        float z[4];
#pragma unroll
        for (int g = 0; g < 4; g++) {
            float s = xv[g];
#pragma unroll
            for (int w = 0; w < 8; w++)
                s += sPart[(((w * 2 + mtD) * 4 + g) * 32 + laneD) * 4 + regD];
            z[g] = s;
        }

        float ig = sig_fast(z[0]);
        float fg = sig_fast(z[1]);
        float gg = tanh_fast(z[2]);
        float og = sig_fast(z[3]);
        c_state = fmaf(fg, c_state, ig * gg);
        float hv = og * tanh_fast(c_state);

        *(unsigned*)&g_hA[wbuf][p_mt][p_kt][p_lane][p_reg] = f2tf32(hv);
        out[((size_t)rb * Tlen + t) * Hdim + j] = hv;

        if (t + 1 < Tlen) {
            const float* nx = xwp + (size_t)(t + 1) * (Bsz * G4);
#pragma unroll
            for (int g = 0; g < 4; g++) xv[g] = __ldg(nx + g * 1024);
        }

        target += NBLK;
        grid_barrier(target);
    }
}

// =======================================================================
extern "C" void kernel_launch(void* const* d_in, const int* in_sizes, int n_in,
                              void* d_out, int out_size)
{
    const float* x    = (const float*)d_in[0];
    const float* Wih  = (const float*)d_in[1];
    const float* Whh  = (const float*)d_in[2];
    const float* bias = (const float*)d_in[3];
    float* out = (float*)d_out;

    cudaFuncSetAttribute(gemm_xw_kernel,
                         cudaFuncAttributeMaxDynamicSharedMemorySize, P1_SMEM);
    cudaFuncSetAttribute(lstm_rec_kernel,
                         cudaFuncAttributeMaxDynamicSharedMemorySize, SMEM_P2);

    prep_kernel<<<2048, 256>>>(x, Wih);

    dim3 g1(G4 / 128, (Bsz * Tlen) / 128);   // (32, 128)
    gemm_xw_kernel<<<g1, 256, P1_SMEM>>>(bias);

    lstm_rec_kernel<<<NBLK, 256, SMEM_P2>>>(Whh, out);
}

// round 14
// speedup vs baseline: 1.0170x; 1.0170x over previous
#include <cuda_runtime.h>
#include <math.h>

#define Bsz  32
#define Tlen 512
#define Idim 1024
#define Hdim 1024
#define G4   4096
#define NBLK2 256

// ---------------- device scratch ----------------
__device__ float g_xw[(size_t)Tlen * Bsz * G4];       // [t][b][4H]
// A fragment-major: [MT 1024][KT 128][lane 32] x float4
__device__ float4 g_xa[(size_t)1024 * 128 * 32];
// B (W_ih) fragment-major: [NT 512][KT2 64][lane 32] x float4
__device__ float4 g_wb[(size_t)512 * 64 * 32];
__device__ float g_hA[2][2][128][32][4];              // h A-frag layout (tf32 bits)
__device__ unsigned int g_bar;

// ---------------- helpers ----------------
__device__ __forceinline__ unsigned f2tf32(float f)
{
    unsigned r;
    asm("cvt.rna.tf32.f32 %0, %1;" : "=r"(r) : "f"(f));
    return r;
}
__device__ __forceinline__ void mma_tf32(float* d, const unsigned* a, const unsigned* b)
{
    asm volatile(
        "mma.sync.aligned.m16n8k8.row.col.f32.tf32.tf32.f32 "
        "{%0,%1,%2,%3},{%4,%5,%6,%7},{%8,%9},{%0,%1,%2,%3};"
        : "+f"(d[0]), "+f"(d[1]), "+f"(d[2]), "+f"(d[3])
        : "r"(a[0]), "r"(a[1]), "r"(a[2]), "r"(a[3]), "r"(b[0]), "r"(b[1]));
}
__device__ __forceinline__ void cp_async16(unsigned dst, const void* src)
{
    asm volatile("cp.async.cg.shared.global [%0], [%1], 16;" :: "r"(dst), "l"(src));
}
#define CP_COMMIT()  asm volatile("cp.async.commit_group;")
#define CP_WAIT(N)   asm volatile("cp.async.wait_group %0;" :: "n"(N))

__device__ __forceinline__ uint4 lds128(unsigned addr)
{
    uint4 v;
    asm volatile("ld.shared.v4.b32 {%0,%1,%2,%3}, [%4];"
                 : "=r"(v.x), "=r"(v.y), "=r"(v.z), "=r"(v.w) : "r"(addr));
    return v;
}
__device__ __forceinline__ float sig_fast(float x)
{
    return __frcp_rn(1.f + __expf(-x));
}
__device__ __forceinline__ float tanh_fast(float x)
{
    return fmaf(2.f, __frcp_rn(1.f + __expf(-2.f * x)), -1.f);
}

// =======================================================================
// Kernel 0: build fragment-major tf32-rounded copies of x and W_ih.
// =======================================================================
__global__ void __launch_bounds__(256) prep_kernel(
    const float* __restrict__ x, const float* __restrict__ Wih)
{
    if (blockIdx.x == 0 && threadIdx.x == 0) g_bar = 0u;
    const size_t NA = (size_t)1024 * 128 * 32;
    const size_t NW = (size_t)512 * 64 * 32;
    size_t i0 = (size_t)blockIdx.x * blockDim.x + threadIdx.x;
    size_t stride = (size_t)gridDim.x * blockDim.x;

    for (size_t i = i0; i < NA; i += stride) {
        int l  = (int)(i & 31);
        int KT = (int)((i >> 5) & 127);
        int MT = (int)(i >> 12);
        int g = l >> 2, tg = l & 3;
        const float* base = x + (size_t)(MT * 16 + g) * Idim + KT * 8 + tg;
        uint4 r;
        r.x = f2tf32(base[0]);
        r.y = f2tf32(base[8 * Idim]);
        r.z = f2tf32(base[4]);
        r.w = f2tf32(base[8 * Idim + 4]);
        *(uint4*)&g_xa[i] = r;
    }
    for (size_t i = i0; i < NW; i += stride) {
        int l   = (int)(i & 31);
        int KT2 = (int)((i >> 5) & 63);
        int NT  = (int)(i >> 11);
        int g = l >> 2, tg = l & 3;
        const float* base = Wih + (size_t)(NT * 8 + g) * Idim + KT2 * 16 + tg;
        uint4 r;
        r.x = f2tf32(base[0]);
        r.y = f2tf32(base[4]);
        r.z = f2tf32(base[8]);
        r.w = f2tf32(base[12]);
        *(uint4*)&g_wb[i] = r;
    }
}

// =======================================================================
// Phase 1 (VERBATIM from the 2783us best run): tf32 mma.sync,
// CTA 128x128, BK=32, 8 warps (2Mx4N), warp tile 64x32, 3-stage ring, occ 2.
// =======================================================================
#define P1_STG    3
#define P1_ABYTES (8 * 4 * 32 * 16)      // 16384
#define P1_BBYTES (16 * 2 * 32 * 16)     // 16384
#define P1_STRIDE (P1_ABYTES + P1_BBYTES)
#define P1_SMEM   (P1_STG * P1_STRIDE)   // 98304

__global__ void __launch_bounds__(256, 2) gemm_xw_kernel(const float* __restrict__ bias)
{
    extern __shared__ float sm[];

    const int tid  = threadIdx.x;
    const int wi   = tid >> 5;
    const int lane = tid & 31;
    const int wm   = wi >> 2;
    const int wn   = wi & 3;
    const int g    = lane >> 2;
    const int tg   = lane & 3;

    const int bn  = blockIdx.x * 128;
    const int bm  = blockIdx.y * 128;
    const int MT0 = blockIdx.y * 8;
    const int NT0 = blockIdx.x * 16;

    const unsigned smb = (unsigned)__cvta_generic_to_shared(sm);

    float D[4][4][4];
#pragma unroll
    for (int mi = 0; mi < 4; mi++)
#pragma unroll
        for (int ni = 0; ni < 4; ni++)
#pragma unroll
            for (int q = 0; q < 4; q++) D[mi][ni][q] = 0.f;

#pragma unroll
    for (int s = 0; s < 2; s++) {
        const unsigned sb = smb + (unsigned)(s * P1_STRIDE);
#pragma unroll
        for (int j = 0; j < 4; j++) {
            int item = tid + j * 256;
            int mt = item >> 7, kt = (item >> 5) & 3, l = item & 31;
            const float4* src = g_xa + ((size_t)(MT0 + mt) * 128 + s * 4 + kt) * 32 + l;
            cp_async16(sb + (unsigned)(item * 16), src);
        }
#pragma unroll
        for (int j = 0; j < 4; j++) {
            int item = tid + j * 256;
            int nt = item >> 6, kt2 = (item >> 5) & 1, l = item & 31;
            const float4* src = g_wb + ((size_t)(NT0 + nt) * 64 + s * 2 + kt2) * 32 + l;
            cp_async16(sb + (unsigned)(P1_ABYTES + item * 16), src);
        }
        CP_COMMIT();
    }

    int buf = 0;
    for (int kc = 0; kc < 32; kc++) {
        if (kc == 31) { CP_WAIT(0); } else { CP_WAIT(1); }
        __syncthreads();

        if (kc + 2 < 32) {
            const int s = (buf + 2) % P1_STG;
            const unsigned sb = smb + (unsigned)(s * P1_STRIDE);
#pragma unroll
            for (int j = 0; j < 4; j++) {
                int item = tid + j * 256;
                int mt = item >> 7, kt = (item >> 5) & 3, l = item & 31;
                const float4* src =
                    g_xa + ((size_t)(MT0 + mt) * 128 + (kc + 2) * 4 + kt) * 32 + l;
                cp_async16(sb + (unsigned)(item * 16), src);
            }
#pragma unroll
            for (int j = 0; j < 4; j++) {
                int item = tid + j * 256;
                int nt = item >> 6, kt2 = (item >> 5) & 1, l = item & 31;
                const float4* src =
                    g_wb + ((size_t)(NT0 + nt) * 64 + (kc + 2) * 2 + kt2) * 32 + l;
                cp_async16(sb + (unsigned)(P1_ABYTES + item * 16), src);
            }
            CP_COMMIT();
        }

        const unsigned Ab = smb + (unsigned)(buf * P1_STRIDE);
        const unsigned Bb = Ab + (unsigned)P1_ABYTES;

#pragma unroll
        for (int kt2 = 0; kt2 < 2; kt2++) {
            uint4 Bp[4];
#pragma unroll
            for (int ni = 0; ni < 4; ni++)
                Bp[ni] = lds128(Bb +
                    (unsigned)((((wn * 4 + ni) * 2 + kt2) * 32 + lane) * 16));
#pragma unroll
            for (int half = 0; half < 2; half++) {
                const int k8 = kt2 * 2 + half;
                uint4 Aq[4];
#pragma unroll
                for (int mi = 0; mi < 4; mi++)
                    Aq[mi] = lds128(Ab +
                        (unsigned)((((wm * 4 + mi) * 4 + k8) * 32 + lane) * 16));
#pragma unroll
                for (int mi = 0; mi < 4; mi++)
#pragma unroll
                    for (int ni = 0; ni < 4; ni++) {
                        unsigned bfrag[2];
                        bfrag[0] = half ? Bp[ni].z : Bp[ni].x;
                        bfrag[1] = half ? Bp[ni].w : Bp[ni].y;
                        mma_tf32(D[mi][ni], (const unsigned*)&Aq[mi], bfrag);
                    }
            }
        }

        buf = (buf + 1) % P1_STG;
    }

    float2 bv[4];
#pragma unroll
    for (int ni = 0; ni < 4; ni++) {
        int j0 = bn + (wn * 4 + ni) * 8 + tg * 2;
        bv[ni].x = __ldg(bias + j0);
        bv[ni].y = __ldg(bias + j0 + 1);
    }
#pragma unroll
    for (int mi = 0; mi < 4; mi++) {
        int r0 = bm + wm * 64 + mi * 16 + g;
        int r1 = r0 + 8;
        int t0 = r0 & (Tlen - 1), b0 = r0 >> 9;
        int t1 = r1 & (Tlen - 1), b1 = r1 >> 9;
        float* base0 = &g_xw[(size_t)t0 * (Bsz * G4) + (size_t)b0 * G4];
        float* base1 = &g_xw[(size_t)t1 * (Bsz * G4) + (size_t)b1 * G4];
#pragma unroll
        for (int ni = 0; ni < 4; ni++) {
            int j0 = bn + (wn * 4 + ni) * 8 + tg * 2;
            float2 v0; v0.x = D[mi][ni][0] + bv[ni].x; v0.y = D[mi][ni][1] + bv[ni].y;
            float2 v1; v1.x = D[mi][ni][2] + bv[ni].x; v1.y = D[mi][ni][3] + bv[ni].y;
            *(float2*)(base0 + j0) = v0;
            *(float2*)(base1 + j0) = v1;
        }
    }
}

// =======================================================================
// Phase 2: persistent recurrence, 256 blocks x 128 threads, occ 2.
// Block bid owns hcols bid*4..+4 x 4 gates = 16 N (2 n-tiles, cols j2=g*4+c).
// 4 warps k-split (32 kt each); c-state per reducer thread (rb=tid>>2, rh=tid&3).
// Two blocks per SM overlap each other's serial tails.
// =======================================================================
#define SWB2_FLOATS  (2 * 128 * 32 * 2)        // 16384 floats = 64 KB
#define SPART2_FLOATS (4 * 2 * 2 * 32 * 4)     // 4096 floats = 16 KB
#define SMEM_P2B ((SWB2_FLOATS + SPART2_FLOATS) * 4)   // 81920

__device__ __forceinline__ void grid_barrier2(unsigned target)
{
    __syncthreads();
    if (threadIdx.x == 0) {
        __threadfence();
        asm volatile("red.release.gpu.global.add.u32 [%0], %1;"
                     :: "l"(&g_bar), "r"(1u) : "memory");
        unsigned v;
        do {
            asm volatile("ld.acquire.gpu.global.u32 %0, [%1];"
                         : "=r"(v) : "l"(&g_bar) : "memory");
        } while (v < target);
    }
    __syncthreads();
}

__global__ void __launch_bounds__(128, 2) lstm_rec_kernel(
    const float* __restrict__ Whh, float* __restrict__ out)
{
    extern __shared__ float smemf[];
    float* sWB   = smemf;                  // [nt 2][kt 128][lane 32][2]
    float* sPart = smemf + SWB2_FLOATS;    // [wi 4][mt 2][nt 2][lane 32][4]

    const int tid  = threadIdx.x;
    const int bid  = blockIdx.x;
    const int wi   = tid >> 5;             // 0..3
    const int lane = tid & 31;

    // ---- build W_hh B-fragments (16 rows: 4 gates x 4 local cols) ----
    for (int idx = tid; idx < 2 * 128 * 32; idx += 128) {
        int l  = idx & 31;
        int kt = (idx >> 5) & 127;
        int nt = idx >> 12;
        int r8 = l >> 2;                   // row within n-tile
        int j2 = nt * 8 + r8;              // 0..15
        int g  = j2 >> 2, c = j2 & 3;
        int row = g * 1024 + bid * 4 + c;
        int k0  = kt * 8 + (l & 3);
        unsigned* dst = (unsigned*)&sWB[((nt * 128 + kt) * 32 + l) * 2];
        dst[0] = f2tf32(Whh[(size_t)row * Hdim + k0]);
        dst[1] = f2tf32(Whh[(size_t)row * Hdim + k0 + 4]);
    }

    // ---- reducer identity: thread owns (batch rb, local col rh) ----
    const int rb = tid >> 2;               // 0..31
    const int rh = tid & 3;                // 0..3
    const int j  = bid * 4 + rh;           // global h index

    const int p_mt   = rb >> 4;
    const int p_kt   = j >> 3;
    const int p_lane = (rb & 7) * 4 + (j & 3);
    const int p_reg  = ((rb & 15) >> 3) + 2 * ((j >> 2) & 1);

    g_hA[0][p_mt][p_kt][p_lane][p_reg] = 0.f;

    const int mtD = rb >> 4;
    // per-gate D coordinates
    int ntD[4], laneD[4], regD[4];
#pragma unroll
    for (int g = 0; g < 4; g++) {
        int j2 = g * 4 + rh;
        int jc = j2 & 7;
        ntD[g]   = j2 >> 3;
        laneD[g] = (rb & 7) * 4 + (jc >> 1);
        regD[g]  = (jc & 1) + 2 * ((rb & 15) >> 3);
    }

    const float* xwp = g_xw + (size_t)rb * G4 + j;
    float xv[4];
#pragma unroll
    for (int g = 0; g < 4; g++) xv[g] = __ldg(xwp + g * 1024);

    float c_state = 0.f;
    unsigned target = NBLK2;
    grid_barrier2(target);

    const int kt0 = wi * 32;

    for (int t = 0; t < Tlen; t++) {
        const int rbuf = t & 1, wbuf = rbuf ^ 1;

        float D[2][2][4];
#pragma unroll
        for (int m = 0; m < 2; m++)
#pragma unroll
            for (int n = 0; n < 2; n++)
#pragma unroll
                for (int q = 0; q < 4; q++) D[m][n][q] = 0.f;

        uint4 A0 = __ldcg((const uint4*)&g_hA[rbuf][0][kt0][lane][0]);
        uint4 A1 = __ldcg((const uint4*)&g_hA[rbuf][1][kt0][lane][0]);
#pragma unroll 8
        for (int i = 0; i < 32; i++) {
            uint4 a0 = A0, a1 = A1;
            if (i < 31) {
                A0 = __ldcg((const uint4*)&g_hA[rbuf][0][kt0 + i + 1][lane][0]);
                A1 = __ldcg((const uint4*)&g_hA[rbuf][1][kt0 + i + 1][lane][0]);
            }
#pragma unroll
            for (int nt = 0; nt < 2; nt++) {
                unsigned bfrag[2];
                *(uint2*)bfrag =
                    *(const uint2*)&sWB[((nt * 128 + kt0 + i) * 32 + lane) * 2];
                mma_tf32(D[0][nt], (const unsigned*)&a0, bfrag);
                mma_tf32(D[1][nt], (const unsigned*)&a1, bfrag);
            }
        }

#pragma unroll
        for (int m = 0; m < 2; m++)
#pragma unroll
            for (int nt = 0; nt < 2; nt++)
                *(float4*)&sPart[(((wi * 2 + m) * 2 + nt) * 32 + lane) * 4] =
                    *(float4*)D[m][nt];
        __syncthreads();

        float z[4];
#pragma unroll
        for (int g = 0; g < 4; g++) {
            float s = xv[g];
#pragma unroll
            for (int w = 0; w < 4; w++)
                s += sPart[(((w * 2 + mtD) * 2 + ntD[g]) * 32 + laneD[g]) * 4 + regD[g]];
            z[g] = s;
        }

        float ig = sig_fast(z[0]);
        float fg = sig_fast(z[1]);
        float gg = tanh_fast(z[2]);
        float og = sig_fast(z[3]);
        c_state = fmaf(fg, c_state, ig * gg);
        float hv = og * tanh_fast(c_state);

        *(unsigned*)&g_hA[wbuf][p_mt][p_kt][p_lane][p_reg] = f2tf32(hv);
        out[((size_t)rb * Tlen + t) * Hdim + j] = hv;

        if (t + 1 < Tlen) {
            const float* nx = xwp + (size_t)(t + 1) * (Bsz * G4);
#pragma unroll
            for (int g = 0; g < 4; g++) xv[g] = __ldg(nx + g * 1024);
        }

        target += NBLK2;
        grid_barrier2(target);
    }
}

// =======================================================================
extern "C" void kernel_launch(void* const* d_in, const int* in_sizes, int n_in,
                              void* d_out, int out_size)
{
    const float* x    = (const float*)d_in[0];
    const float* Wih  = (const float*)d_in[1];
    const float* Whh  = (const float*)d_in[2];
    const float* bias = (const float*)d_in[3];
    float* out = (float*)d_out;

    cudaFuncSetAttribute(gemm_xw_kernel,
                         cudaFuncAttributeMaxDynamicSharedMemorySize, P1_SMEM);
    cudaFuncSetAttribute(lstm_rec_kernel,
                         cudaFuncAttributeMaxDynamicSharedMemorySize, SMEM_P2B);

    prep_kernel<<<2048, 256>>>(x, Wih);

    dim3 g1(G4 / 128, (Bsz * Tlen) / 128);   // (32, 128)
    gemm_xw_kernel<<<g1, 256, P1_SMEM>>>(bias);

    lstm_rec_kernel<<<NBLK2, 128, SMEM_P2B>>>(Whh, out);
}